// round 14
// baseline (speedup 1.0000x reference)
#include <cuda_runtime.h>

#define BB 32
#define NN 1024
#define FF 7
#define HID 256
#define MLPH 64
#define OUTD 8
#define THR2 0.09f
#define KCH 128         // K-chunks for MLP layer0
#define K4  14          // float4s per chunk (56 floats); 128*56 = 7168
#define SEGS 16         // kB segments per batch (64 rows each)
#define CAT (MLPH + HID + OUTD)   // 328
#define PBLK 512        // pair blocks: 16 per batch (4 row-groups x 4 j-groups)

// ---- device scratch ----
__device__ unsigned g_adj[BB * NN * 32];        // adjacency bitmask, 4MB
__device__ float4   g_pack[BB * NN];            // (x, y, -, speed) per node
__device__ int      g_degp[4 * BB * NN];        // degree partials per j-group
__device__ float    g_maxp[BB * 16];            // per-pair-block max dist^2 partials
__device__ float    g_upart[BB * SEGS * HID];   // per-seg partials of sum_j s_j h_j
__device__ float    g_speedp[BB * SEGS];        // per-seg speed sums
__device__ float    g_mpart[KCH * BB * MLPH];   // MLP layer0 K-chunk partials

// sbuf must cover MLP path: 14*64*4 + 14*32*4 floats = 21.5KB
#define SBUF_F (K4 * MLPH * 4 + K4 * BB * 4 + 16)

// ============================================================================
// kA: blocks [0,512): pairwise adjacency, lane-per-row, j-tiled 4-way.
//     blocks [512,640): MLP0 chunk GEMM.
// ============================================================================
__global__ __launch_bounds__(256, 5) void kA(const float* __restrict__ x,
                                             const float* __restrict__ Wm0) {
    __shared__ float sbuf[SBUF_F];
    int t = threadIdx.x;

    if (blockIdx.x < PBLK) {
        float2*   s_pts   = (float2*)sbuf;                    // [256] j-points
        unsigned* s_words = (unsigned*)(sbuf + 512);          // [256][9] padded
        float*    s_max   = sbuf + 512 + 256 * 9;             // [8]
        int b   = blockIdx.x >> 4;
        int sub = blockIdx.x & 15;
        int rg = sub >> 2, jg = sub & 3;
        int row0 = rg << 8, j0 = jg << 8;
        int lane = t & 31, w = t >> 5;

        {   // stage this block's 256 j-points
            const float* xr = x + ((size_t)b * NN + j0 + t) * FF;
            s_pts[t] = make_float2(xr[1], xr[2]);
        }
        __syncthreads();

        int row = row0 + t;
        const float* xrow = x + ((size_t)b * NN + row) * FF;
        float xi = xrow[1], yi = xrow[2];
        float mx = 0.f;
        int deg = 0;
        unsigned* swr = s_words + t * 9;

#pragma unroll
        for (int jw = 0; jw < 8; ++jw) {
            const float4* p4 = (const float4*)(s_pts + jw * 32);
            unsigned word = 0;
#pragma unroll
            for (int k = 0; k < 16; ++k) {
                float4 pp = p4[k];                    // 2 points, warp-broadcast
                float dx = xi - pp.x, dy = yi - pp.y;
                float d2 = fmaf(dx, dx, dy * dy);
                mx = fmaxf(mx, d2);
                if (d2 < THR2) word |= (1u << (2 * k));
                dx = xi - pp.z; dy = yi - pp.w;
                d2 = fmaf(dx, dx, dy * dy);
                mx = fmaxf(mx, d2);
                if (d2 < THR2) word |= (1u << (2 * k + 1));
            }
            swr[jw] = word;
            deg += __popc(word);
        }

        g_degp[((size_t)jg * BB + b) * NN + row] = deg;
        if (jg == 0) {
            float s3 = xrow[3], s4 = xrow[4];
            g_pack[b * NN + row] = make_float4(
                xi, yi, 0.f, sqrtf(fmaf(s3, s3, s4 * s4)));
        }

        for (int o = 16; o > 0; o >>= 1)
            mx = fmaxf(mx, __shfl_xor_sync(0xffffffffu, mx, o));
        if (lane == 0) s_max[w] = mx;
        __syncthreads();
        if (t == 0) {
            float m = s_max[0];
#pragma unroll
            for (int k = 1; k < 8; ++k) m = fmaxf(m, s_max[k]);
            g_maxp[b * 16 + sub] = m;
        }

        // copy adjacency words (8 per row) to row-major g_adj
        unsigned* dst = g_adj + ((size_t)b * NN + row0) * 32 + jg * 8;
        for (int idx = t; idx < 256 * 8; idx += 256) {
            int r = idx >> 3, wi = idx & 7;
            dst[(size_t)r * 32 + wi] = s_words[r * 9 + wi];
        }
    } else {
        int c = blockIdx.x - PBLK;
        float4* sw4 = (float4*)sbuf;                       // [K4][64]
        float4* sx4 = (float4*)(sbuf + K4 * MLPH * 4);     // [K4][32]
        const float4* W4 = (const float4*)Wm0;
        const float4* X4 = (const float4*)x;

        for (int i = t; i < MLPH * K4; i += 256) {
            int h = i / K4, k = i % K4;
            sw4[k * MLPH + h] = W4[(size_t)h * 1792 + c * K4 + k];
        }
        for (int i = t; i < BB * K4; i += 256) {
            int b = i / K4, k = i % K4;
            sx4[k * BB + b] = X4[(size_t)b * 1792 + c * K4 + k];
        }
        __syncthreads();

        int hb = t & 15;
        int bbase = t >> 4;
        float acc[2][4] = {};
#pragma unroll
        for (int k = 0; k < K4; ++k) {
            float4 xv[2];
#pragma unroll
            for (int i = 0; i < 2; ++i) xv[i] = sx4[k * BB + bbase + 16 * i];
#pragma unroll
            for (int j = 0; j < 4; ++j) {
                float4 wv = sw4[k * MLPH + hb + 16 * j];
#pragma unroll
                for (int i = 0; i < 2; ++i) {
                    acc[i][j] = fmaf(xv[i].x, wv.x, acc[i][j]);
                    acc[i][j] = fmaf(xv[i].y, wv.y, acc[i][j]);
                    acc[i][j] = fmaf(xv[i].z, wv.z, acc[i][j]);
                    acc[i][j] = fmaf(xv[i].w, wv.w, acc[i][j]);
                }
            }
        }
#pragma unroll
        for (int i = 0; i < 2; ++i)
#pragma unroll
            for (int j = 0; j < 4; ++j)
                g_mpart[((size_t)c * BB + bbase + 16 * i) * MLPH + hb + 16 * j] = acc[i][j];
    }
}

// ============================================================================
// kB: sparse graph pass, warp-per-row. Block = (batch, 64-row segment).
// dinv computed here from the 4 degree partials (fixed order).
// ============================================================================
__global__ __launch_bounds__(256) void kB(const float* __restrict__ W1,
                                          const float* __restrict__ b1) {
    __shared__ float4 s_pack[NN];    // 16KB
    __shared__ float4 s_P[64];
    __shared__ float  sred[64];
    int b = blockIdx.x >> 4, seg = blockIdx.x & 15;
    int row0 = seg * 64;
    int t = threadIdx.x, lane = t & 31, w = t >> 5;

    const float4* packb = g_pack + (size_t)b * NN;
    for (int j = t; j < NN; j += 256) {
        float4 p = packb[j];
        int d = g_degp[((size_t)0 * BB + b) * NN + j]
              + g_degp[((size_t)1 * BB + b) * NN + j]
              + g_degp[((size_t)2 * BB + b) * NN + j]
              + g_degp[((size_t)3 * BB + b) * NN + j];
        p.z = rsqrtf((float)d);
        s_pack[j] = p;
    }
    __syncthreads();

#pragma unroll
    for (int rr = 0; rr < 8; ++rr) {
        int row = row0 + w * 8 + rr;
        unsigned m = g_adj[((size_t)b * NN + row) * 32 + lane];
        float wsum = 0.f, px = 0.f, py = 0.f;
        int base = lane * 32;
        while (m) {
            int j = base + __ffs(m) - 1;
            m &= m - 1;
            float4 p = s_pack[j];
            wsum += p.z;
            px = fmaf(p.z, p.x, px);
            py = fmaf(p.z, p.y, py);
        }
#pragma unroll
        for (int o = 16; o > 0; o >>= 1) {
            px   += __shfl_xor_sync(0xffffffffu, px, o);
            py   += __shfl_xor_sync(0xffffffffu, py, o);
            wsum += __shfl_xor_sync(0xffffffffu, wsum, o);
        }
        if (lane == 0) {
            float di = s_pack[row].z;
            s_P[w * 8 + rr] = make_float4(di * px, di * py, di * wsum, 0.f);
        }
    }
    if (t < 64) sred[t] = s_pack[row0 + t].w;
    __syncthreads();

    for (int o = 32; o > 0; o >>= 1) {
        if (t < o) sred[t] += sred[t + o];
        __syncthreads();
    }
    if (t == 0) g_speedp[b * SEGS + seg] = sred[0];

    float w10 = W1[2 * t], w11 = W1[2 * t + 1], bk = b1[t];
    float acc = 0.f;
#pragma unroll 8
    for (int r = 0; r < 64; ++r) {
        float4 P = s_P[r];
        float h = fmaxf(fmaf(w10, P.x, fmaf(w11, P.y, bk)), 0.f);
        acc = fmaf(P.z, h, acc);
    }
    g_upart[((size_t)b * SEGS + seg) * HID + t] = acc;
}

// ============================================================================
// k3: per-batch finals — all matvecs warp-per-row, coalesced, shuffle reduce.
// ============================================================================
__global__ __launch_bounds__(256) void k3_final(
                         const float* __restrict__ W2,  const float* __restrict__ b2,
                         const float* __restrict__ Wfc, const float* __restrict__ bfc,
                         const float* __restrict__ Wg,  const float* __restrict__ bg,
                         const float* __restrict__ Wm1, const float* __restrict__ bm1,
                         const float* __restrict__ bm0,
                         const float* __restrict__ Wp,  const float* __restrict__ bp,
                         float* __restrict__ out) {
    __shared__ __align__(16) float sm[HID];
    __shared__ __align__(16) float smid[HID];
    __shared__ float sy0p[4][MLPH];
    __shared__ __align__(16) float sy0[MLPH];
    __shared__ __align__(16) float svec[CAT];   // [sy1(64) | sgcn(256) | sglo(8)]
    int b = blockIdx.x, t = threadIdx.x, lane = t & 31, w = t >> 5;

    float u = 0.f;
#pragma unroll
    for (int c = 0; c < SEGS; ++c) u += g_upart[((size_t)b * SEGS + c) * HID + t];
    sm[t] = u * (1.0f / 1024.0f);

    {
        int h = t & 63, grp = t >> 6;
        float a = 0.f;
#pragma unroll 8
        for (int k = 0; k < KCH / 4; ++k)
            a += g_mpart[((size_t)(grp * (KCH / 4) + k) * BB + b) * MLPH + h];
        sy0p[grp][h] = a;
    }
    __syncthreads();
    if (t < MLPH)
        sy0[t] = fmaxf(sy0p[0][t] + sy0p[1][t] + sy0p[2][t] + sy0p[3][t] + bm0[t], 0.f);
    __syncthreads();

#pragma unroll
    for (int k = 0; k < 8; ++k) {
        int r = w * 8 + k;
        float v = fmaf(Wm1[r * MLPH + lane], sy0[lane],
                       Wm1[r * MLPH + 32 + lane] * sy0[32 + lane]);
#pragma unroll
        for (int o = 16; o > 0; o >>= 1) v += __shfl_xor_sync(0xffffffffu, v, o);
        if (lane == 0) svec[r] = fmaxf(v + bm1[r], 0.f);
    }

    const float4* sm4 = (const float4*)sm;
    float4 m0 = sm4[lane], m1 = sm4[lane + 32];
#pragma unroll 4
    for (int k = 0; k < 32; ++k) {
        int r = w * 32 + k;
        const float4* wr = (const float4*)(W2 + (size_t)r * HID);
        float4 w0 = wr[lane], w1 = wr[lane + 32];
        float v = w0.x * m0.x + w0.y * m0.y + w0.z * m0.z + w0.w * m0.w
                + w1.x * m1.x + w1.y * m1.y + w1.z * m1.z + w1.w * m1.w;
#pragma unroll
        for (int o = 16; o > 0; o >>= 1) v += __shfl_xor_sync(0xffffffffu, v, o);
        if (lane == 0) smid[r] = v + b2[r];
    }
    __syncthreads();

    const float4* sd4 = (const float4*)smid;
    float4 d0 = sd4[lane], d1 = sd4[lane + 32];
#pragma unroll 4
    for (int k = 0; k < 32; ++k) {
        int r = w * 32 + k;
        const float4* wr = (const float4*)(Wfc + (size_t)r * HID);
        float4 w0 = wr[lane], w1 = wr[lane + 32];
        float v = w0.x * d0.x + w0.y * d0.y + w0.z * d0.z + w0.w * d0.w
                + w1.x * d1.x + w1.y * d1.y + w1.z * d1.z + w1.w * d1.w;
#pragma unroll
        for (int o = 16; o > 0; o >>= 1) v += __shfl_xor_sync(0xffffffffu, v, o);
        if (lane == 0) svec[MLPH + r] = v + bfc[r];
    }

    if (t < OUTD) {
        float avg = 0.f;
#pragma unroll
        for (int c = 0; c < SEGS; ++c) avg += g_speedp[b * SEGS + c];
        avg *= (1.0f / 1024.0f);
        float mx = g_maxp[b * 16];
#pragma unroll
        for (int k = 1; k < 16; ++k) mx = fmaxf(mx, g_maxp[b * 16 + k]);
        float den = rsqrtf(mx);
        svec[MLPH + HID + t] =
            fmaxf(fmaf(Wg[t * 2], avg, fmaf(Wg[t * 2 + 1], den, bg[t])), 0.f);
    }
    __syncthreads();

    if (w < OUTD) {
        const float* wp = Wp + (size_t)w * CAT;
        float o = 0.f;
#pragma unroll
        for (int j = lane; j < CAT; j += 32) o = fmaf(wp[j], svec[j], o);
#pragma unroll
        for (int s = 16; s > 0; s >>= 1) o += __shfl_xor_sync(0xffffffffu, o, s);
        if (lane == 0) out[b * OUTD + w] = o + bp[w];
    }
}

extern "C" void kernel_launch(void* const* d_in, const int* in_sizes, int n_in,
                              void* d_out, int out_size) {
    const float* x   = (const float*)d_in[0];
    const float* W1  = (const float*)d_in[1];
    const float* b1  = (const float*)d_in[2];
    const float* W2  = (const float*)d_in[3];
    const float* b2  = (const float*)d_in[4];
    const float* Wfc = (const float*)d_in[5];
    const float* bfc = (const float*)d_in[6];
    const float* Wg  = (const float*)d_in[7];
    const float* bg  = (const float*)d_in[8];
    const float* Wm0 = (const float*)d_in[9];
    const float* bm0 = (const float*)d_in[10];
    const float* Wm1 = (const float*)d_in[11];
    const float* bm1 = (const float*)d_in[12];
    const float* Wp  = (const float*)d_in[13];
    const float* bp  = (const float*)d_in[14];
    float* out = (float*)d_out;

    kA<<<PBLK + KCH, 256>>>(x, Wm0);
    kB<<<512, 256>>>(W1, b1);
    k3_final<<<32, 256>>>(W2, b2, Wfc, bfc, Wg, bg, Wm1, bm1, bm0, Wp, bp, out);
}